// round 16
// baseline (speedup 1.0000x reference)
#include <cuda_runtime.h>

// LSTM: B=4096, T=512, I=3, H=32, C=3
// R14: 2-warp gate-split blocks. warp0 computes gates {i,f}, warp1 {g,o},
//      each over all NB=4 batches (4 fma2 chains x 32 deep per warp).
//      Per-step SMEM exchange of half the pre-activations; each warp owns
//      c/h for 2 batches. Doubles resident warps/SM (13.8, single wave)
//      at constant per-SMSP fma-pipe load. Math identical to R10.

#define FULL_MASK 0xffffffffu
typedef unsigned long long ull;

constexpr int B_DIM  = 4096;
constexpr int T_DIM  = 512;
constexpr int H_DIM  = 32;
constexpr int NB     = 4;     // batches per block
constexpr int NTHREADS = 64;  // 2 warps
constexpr int CHUNK  = 32;    // timesteps per staged chunk
constexpr int NCHUNK = T_DIM / CHUNK;  // 16

__device__ __forceinline__ float tanh_fast(float x) {
    float y;
    asm("tanh.approx.f32 %0, %1;" : "=f"(y) : "f"(x));
    return y;
}
__device__ __forceinline__ ull pack2(float lo, float hi) {
    ull r;
    asm("mov.b64 %0, {%1, %2};"
        : "=l"(r) : "r"(__float_as_uint(lo)), "r"(__float_as_uint(hi)));
    return r;
}
__device__ __forceinline__ void unpack2(ull v, float& lo, float& hi) {
    unsigned int a, b;
    asm("mov.b64 {%0, %1}, %2;" : "=r"(a), "=r"(b) : "l"(v));
    lo = __uint_as_float(a);
    hi = __uint_as_float(b);
}
__device__ __forceinline__ void fma2(ull& acc, ull a, ull b) {
    asm("fma.rn.f32x2 %0, %1, %2, %0;" : "+l"(acc) : "l"(a), "l"(b));
}
__device__ __forceinline__ ull fma2o(ull a, ull b, ull c) {
    ull d;
    asm("fma.rn.f32x2 %0, %1, %2, %3;" : "=l"(d) : "l"(a), "l"(b), "l"(c));
    return d;
}

// activation + cell update for one batch; preacts for i,f,o pre-scaled by 0.5
__device__ __forceinline__ void do_act(ull pre_if, ull pre_go, float& c, float& h) {
    float pi, pf, pg, po;
    unpack2(pre_if, pi, pf);
    unpack2(pre_go, pg, po);
    float ig = fmaf(0.5f, tanh_fast(pi), 0.5f);
    float fg = fmaf(0.5f, tanh_fast(pf), 0.5f);
    float gg = tanh_fast(pg);
    float og = fmaf(0.5f, tanh_fast(po), 0.5f);
    c = fmaf(fg, c, ig * gg);
    h = og * tanh_fast(c);
}

__global__ void __launch_bounds__(NTHREADS)
lstm_fused_kernel(const float* __restrict__ x,      // (B,T,3)
                  const float* __restrict__ W_ih,   // (128,3)
                  const float* __restrict__ W_hh,   // (128,32)
                  const float* __restrict__ b_ih,   // (128,)
                  const float* __restrict__ b_hh,   // (128,)
                  const float* __restrict__ W_fc,   // (3,32)
                  const float* __restrict__ b_fc,   // (3,)
                  float* __restrict__ out)          // (B,3)
{
    // duplicated x: per (batch, t): {x0,x0,x1,x1} {x2,x2,_,_} -> 2 float4 (4 KB)
    __shared__ float4 sxd[NB][CHUNK][2];
    // duplicated h, double-buffered: shb[pb][j][0]={h0,h0,h1,h1}, [1]={h2,h2,h3,h3} (2 KB)
    __shared__ float4 shb[2][H_DIM][2];
    // preact exchange: spre[0][lane] = warp0's {i,f} for batches 2,3
    //                  spre[1][lane] = warp1's {g,o} for batches 0,1   (1 KB)
    __shared__ ulonglong2 spre[2][H_DIM];

    const int tid  = threadIdx.x;
    const int lane = tid & 31;
    const int warp = tid >> 5;
    const int b0   = blockIdx.x * NB;

    // ---- this warp's gate pair: warp0 -> rows (lane, 32+lane) = {i,f}
    //                              warp1 -> rows (64+lane, 96+lane) = {g,o}
    const int r0 = (warp * 2 + 0) * 32 + lane;
    const int r1 = (warp * 2 + 1) * 32 + lane;
    const float s0 = (warp == 1) ? 1.0f : 0.5f;   // g unscaled; i scaled
    const float s1 = 0.5f;                        // f and o scaled

    // ---- W_hh pair rows straight into registers (32 ull = 64 regs) ----
    ull w[H_DIM];
    {
        const float* p0 = W_hh + r0 * H_DIM;
        const float* p1 = W_hh + r1 * H_DIM;
#pragma unroll
        for (int j = 0; j < H_DIM; j++)
            w[j] = pack2(p0[j] * s0, p1[j] * s1);
    }

    // ---- input weights + combined bias, packed per gate pair ----
    ull wp[3], bias;
#pragma unroll
    for (int k = 0; k < 3; k++)
        wp[k] = pack2(W_ih[r0 * 3 + k] * s0, W_ih[r1 * 3 + k] * s1);
    bias = pack2((b_ih[r0] + b_hh[r0]) * s0, (b_ih[r1] + b_hh[r1]) * s1);

    // init h buffer 0 (warp0 slot 0, warp1 slot 1)
    shb[0][lane][warp] = make_float4(0.f, 0.f, 0.f, 0.f);
    __syncthreads();

    // c/h state: warp0 owns batches 0,1; warp1 owns batches 2,3
    float c0 = 0.f, c1 = 0.f, h0 = 0.f, h1 = 0.f;

    const float4* xv = reinterpret_cast<const float4*>(x);
    int pb = 0;

    for (int k = 0; k < NCHUNK; k++) {
        // ---- stage x chunk, duplicated (96 gmem float4, 64 threads) ----
#pragma unroll
        for (int idx = tid; idx < 96; idx += NTHREADS) {
            int n = idx / 24, rem = idx % 24;
            float4 v = xv[(size_t)(b0 + n) * (T_DIM * 3 / 4) + k * 24 + rem];
            const float* ve = &v.x;
            float* base = reinterpret_cast<float*>(&sxd[n][0][0]);
#pragma unroll
            for (int e = 0; e < 4; e++) {
                int flat = rem * 4 + e;           // 0..95
                int t = flat / 3, cmp = flat - 3 * t;
                base[t * 8 + cmp * 2 + 0] = ve[e];
                base[t * 8 + cmp * 2 + 1] = ve[e];
            }
        }
        __syncthreads();

#pragma unroll 1
        for (int tt = 0; tt < CHUNK; tt++) {
            // ---- input projection: this warp's 2 gates, all 4 batches ----
            ull acc[NB];
#pragma unroll
            for (int n = 0; n < NB; n++) {
                const ulonglong2 xa =
                    *reinterpret_cast<const ulonglong2*>(&sxd[n][tt][0]); // {x0x0,x1x1}
                const ull xb =
                    *reinterpret_cast<const ull*>(&sxd[n][tt][1]);        // {x2x2}
                ull a = fma2o(wp[0], xa.x, bias);
                a = fma2o(wp[1], xa.y, a);
                a = fma2o(wp[2], xb, a);
                acc[n] = a;
            }

            // ---- recurrent matvec: 4 chains x 32, h via broadcast LDS.128 ----
            {
                const ulonglong2* hb =
                    reinterpret_cast<const ulonglong2*>(&shb[pb][0][0]);
#pragma unroll
                for (int j = 0; j < H_DIM; j++) {
                    ulonglong2 ha = hb[j * 2 + 0];  // {h0,h0} {h1,h1}
                    ulonglong2 hc = hb[j * 2 + 1];  // {h2,h2} {h3,h3}
                    fma2(acc[0], w[j], ha.x);
                    fma2(acc[1], w[j], ha.y);
                    fma2(acc[2], w[j], hc.x);
                    fma2(acc[3], w[j], hc.y);
                }
            }

            // ---- exchange: publish the half the other warp finalizes ----
            if (warp == 0) {
                ulonglong2 p; p.x = acc[2]; p.y = acc[3];   // {i,f} for b2,b3
                spre[0][lane] = p;
            } else {
                ulonglong2 p; p.x = acc[0]; p.y = acc[1];   // {g,o} for b0,b1
                spre[1][lane] = p;
            }
            __syncthreads();
            const ulonglong2 other = spre[warp ^ 1][lane];

            // ---- activations + cell update for this warp's 2 batches ----
            if (warp == 0) {
                do_act(acc[0], other.x, c0, h0);   // batch 0: mine={i,f}, other={g,o}
                do_act(acc[1], other.y, c1, h1);   // batch 1
            } else {
                do_act(other.x, acc[2], c0, h0);   // batch 2: other={i,f}, mine={g,o}
                do_act(other.y, acc[3], c1, h1);   // batch 3
            }

            // ---- publish duplicated h for owned batches ----
            shb[pb ^ 1][lane][warp] = make_float4(h0, h0, h1, h1);
            __syncthreads();
            pb ^= 1;
        }
    }

    // ---- final FC for this warp's 2 batches (b0 + 2*warp + {0,1}) ----
    const float wfc0 = W_fc[0 * H_DIM + lane];
    const float wfc1 = W_fc[1 * H_DIM + lane];
    const float wfc2 = W_fc[2 * H_DIM + lane];
#pragma unroll
    for (int n = 0; n < 2; n++) {
        float hn = (n == 0) ? h0 : h1;
        float v0 = hn * wfc0;
        float v1 = hn * wfc1;
        float v2 = hn * wfc2;
#pragma unroll
        for (int off = 16; off > 0; off >>= 1) {
            v0 += __shfl_xor_sync(FULL_MASK, v0, off);
            v1 += __shfl_xor_sync(FULL_MASK, v1, off);
            v2 += __shfl_xor_sync(FULL_MASK, v2, off);
        }
        if (lane == 0) {
            int b = b0 + warp * 2 + n;
            out[b * 3 + 0] = v0 + b_fc[0];
            out[b * 3 + 1] = v1 + b_fc[1];
            out[b * 3 + 2] = v2 + b_fc[2];
        }
    }
}

extern "C" void kernel_launch(void* const* d_in, const int* in_sizes, int n_in,
                              void* d_out, int out_size) {
    const float* x    = (const float*)d_in[0];
    const float* W_ih = (const float*)d_in[1];
    const float* W_hh = (const float*)d_in[2];
    const float* b_ih = (const float*)d_in[3];
    const float* b_hh = (const float*)d_in[4];
    const float* W_fc = (const float*)d_in[5];
    const float* b_fc = (const float*)d_in[6];
    float* out = (float*)d_out;

    const int grid = B_DIM / NB;  // 1024 two-warp blocks
    lstm_fused_kernel<<<grid, NTHREADS>>>(x, W_ih, W_hh, b_ih, b_hh, W_fc, b_fc, out);
}